// round 3
// baseline (speedup 1.0000x reference)
#include <cuda_runtime.h>
#include <math_constants.h>

#define N_SPAT 8000
#define CIN 64
#define DQK 8
#define DV 64
#define LOG2E_F 1.4426950408889634f

// ---------------- scratch (no allocations allowed) ----------------
__device__ float g_Q[2 * N_SPAT * DQK];   // [b][i][c8]
__device__ float g_K[2 * N_SPAT * DQK];   // [b][j][c8]
__device__ float g_V[2 * N_SPAT * DV];    // [b][j][c64]

// ---------------- f32x2 helpers (FFMA2 path, sm_10x) ----------------
__device__ __forceinline__ unsigned long long dup2(float x) {
    unsigned long long r;
    asm("mov.b64 %0, {%1, %1};" : "=l"(r) : "r"(__float_as_uint(x)));
    return r;
}
__device__ __forceinline__ unsigned long long pack2(float lo, float hi) {
    unsigned long long r;
    asm("mov.b64 %0, {%1, %2};" : "=l"(r) : "r"(__float_as_uint(lo)), "r"(__float_as_uint(hi)));
    return r;
}
__device__ __forceinline__ void fma2(unsigned long long& d, unsigned long long a, unsigned long long b) {
    asm("fma.rn.f32x2 %0, %1, %2, %0;" : "+l"(d) : "l"(a), "l"(b));
}
__device__ __forceinline__ unsigned long long mul2(unsigned long long a, unsigned long long b) {
    unsigned long long r;
    asm("mul.rn.f32x2 %0, %1, %2;" : "=l"(r) : "l"(a), "l"(b));
    return r;
}
__device__ __forceinline__ float lo32(unsigned long long v) { return __uint_as_float((unsigned)v); }
__device__ __forceinline__ float hi32(unsigned long long v) { return __uint_as_float((unsigned)(v >> 32)); }

// ---------------- cp.async helpers ----------------
__device__ __forceinline__ void cp_async16(void* smem, const void* gmem) {
    unsigned saddr = (unsigned)__cvta_generic_to_shared(smem);
    asm volatile("cp.async.cg.shared.global [%0], [%1], 16;\n" :: "r"(saddr), "l"(gmem));
}
__device__ __forceinline__ void cp_commit() { asm volatile("cp.async.commit_group;\n"); }
__device__ __forceinline__ void cp_wait0() { asm volatile("cp.async.wait_group 0;\n"); }

// =====================================================================
// Conv kernel: fused Q/K/V 3x3x3 SAME conv.
// Grid (5 ocGroups, 20 z, 2 b), block 400 (one thread per (y,x)).
// Padded 22x22 slab (no per-tap predicates), vectorized 16B stores.
// =====================================================================
#define CONV_T 400
#define ICCHUNK 4
#define PS 484    // 22*22 padded slab

__global__ __launch_bounds__(CONV_T) void conv_qkv_kernel(
    const float* __restrict__ x,
    const float* __restrict__ wq, const float* __restrict__ bq,
    const float* __restrict__ wk, const float* __restrict__ bk,
    const float* __restrict__ wv, const float* __restrict__ bv)
{
    __shared__ __align__(16) float slab[ICCHUNK][3][PS];
    __shared__ __align__(16) float wsm[ICCHUNK][27][16];

    const int g = blockIdx.x;
    const int z = blockIdx.y;
    const int b = blockIdx.z;
    const int tid = threadIdx.x;           // 0..399 == spatial (y,x)
    const int y = tid / 20;
    const int xc = tid % 20;
    const int ocbase = g * 16;

    unsigned long long acc[8];
#pragma unroll
    for (int o2 = 0; o2 < 8; ++o2) {
        int oc0 = ocbase + 2 * o2, oc1 = oc0 + 1;
        float b0 = (oc0 < 8) ? bq[oc0] : (oc0 < 16 ? bk[oc0 - 8] : bv[oc0 - 16]);
        float b1 = (oc1 < 8) ? bq[oc1] : (oc1 < 16 ? bk[oc1 - 8] : bv[oc1 - 16]);
        acc[o2] = pack2(b0, b1);
    }

    for (int chunk = 0; chunk < CIN / ICCHUNK; ++chunk) {
        __syncthreads();
        // fill padded input slab (zero borders)
        for (int idx = tid; idx < ICCHUNK * 3 * PS; idx += CONV_T) {
            int spl = idx % PS;
            int zz = (idx / PS) % 3;
            int ic = idx / (3 * PS);
            int yy = spl / 22 - 1;
            int xx = spl % 22 - 1;
            int zg = z + zz - 1;
            float v = 0.f;
            if ((unsigned)zg < 20u && (unsigned)yy < 20u && (unsigned)xx < 20u)
                v = x[(((size_t)b * 64 + chunk * ICCHUNK + ic) * 20 + zg) * 400 + yy * 20 + xx];
            slab[ic][zz][spl] = v;
        }
        // fill weights [ic][tap][ocl]  (oc pairs contiguous for f32x2)
        for (int idx = tid; idx < ICCHUNK * 27 * 16; idx += CONV_T) {
            int ocl = idx & 15;
            int tap = (idx >> 4) % 27;
            int ic = idx / (27 * 16);
            int oc = ocbase + ocl;
            int icg = chunk * ICCHUNK + ic;
            float w;
            if (oc < 8)       w = wq[((size_t)oc * 64 + icg) * 27 + tap];
            else if (oc < 16) w = wk[((size_t)(oc - 8) * 64 + icg) * 27 + tap];
            else              w = wv[((size_t)(oc - 16) * 64 + icg) * 27 + tap];
            wsm[ic][tap][ocl] = w;
        }
        __syncthreads();

#pragma unroll
        for (int ic = 0; ic < ICCHUNK; ++ic) {
#pragma unroll
            for (int dz = 0; dz < 3; ++dz) {
                const float* sl = &slab[ic][dz][y * 22 + xc];
#pragma unroll
                for (int t9 = 0; t9 < 9; ++t9) {
                    const int dy = t9 / 3, dx = t9 % 3;
                    unsigned long long xd = dup2(sl[dy * 22 + dx]);
                    const unsigned long long* wp =
                        (const unsigned long long*)&wsm[ic][dz * 9 + t9][0];
#pragma unroll
                    for (int o2 = 0; o2 < 8; ++o2) fma2(acc[o2], wp[o2], xd);
                }
            }
        }
    }

    // vectorized stores: thread owns 16 consecutive channels for its voxel
    const int i = z * 400 + tid;
    if (g == 0) {
        float4 a0 = make_float4(lo32(acc[0]), hi32(acc[0]), lo32(acc[1]), hi32(acc[1]));
        float4 a1 = make_float4(lo32(acc[2]), hi32(acc[2]), lo32(acc[3]), hi32(acc[3]));
        float4 a2 = make_float4(lo32(acc[4]), hi32(acc[4]), lo32(acc[5]), hi32(acc[5]));
        float4 a3 = make_float4(lo32(acc[6]), hi32(acc[6]), lo32(acc[7]), hi32(acc[7]));
        float4* qd = (float4*)(g_Q + ((size_t)b * N_SPAT + i) * DQK);
        qd[0] = a0; qd[1] = a1;
        float4* kd = (float4*)(g_K + ((size_t)b * N_SPAT + i) * DQK);
        kd[0] = a2; kd[1] = a3;
    } else {
        float4* vd = (float4*)(g_V + ((size_t)b * N_SPAT + i) * DV + (g - 1) * 16);
#pragma unroll
        for (int q = 0; q < 4; ++q)
            vd[q] = make_float4(lo32(acc[2 * q]), hi32(acc[2 * q]),
                                lo32(acc[2 * q + 1]), hi32(acc[2 * q + 1]));
    }
}

// =====================================================================
// Flash attention kernel. BM=64 rows/CTA (grid 125x2 -> occ>=2/SM),
// BN=64 cols/tile, 128 threads, 4x8 micro-tile.
// Phase A scalar FFMA (k=8); softmax MUFU exp2 (base-2, Q pre-scaled);
// P exchanged through padded smem tile (intra-warp -> __syncwarp only);
// Phase C: broadcast LDS of P + V, FFMA2 into 4x8 O micro-tile.
// K/V tiles double-buffered (K via LDG->STS transpose, V via cp.async).
// Dynamic smem layout (floats):
//   sQT  [8][64]        @ 0      (512)
//   sKT  [2][8][64]     @ 512    (1024)
//   sV   [2][64][64]    @ 1536   (8192)   (sV[0] reused as epilogue staging)
//   sP   [64][72]       @ 9728   (4608)
// total 14336 floats = 57344 bytes
// =====================================================================
#define BM 64
#define BN 64
#define ATT_T 128
#define SMEM_ATT_BYTES (14336 * 4)
#define PSTRIDE 72

__global__ __launch_bounds__(ATT_T, 2) void attn_kernel(float* __restrict__ out)
{
    extern __shared__ __align__(16) float dyn[];
    float* sQT = dyn;             // [k][i]
    float* sKT = dyn + 512;       // [buf][k][j]
    float* sV  = dyn + 1536;      // [buf][j][c]
    float* sP  = dyn + 9728;      // [row][k], stride 72

    const int b = blockIdx.y;
    const int i0 = blockIdx.x * BM;
    const int tid = threadIdx.x;
    const int tc = tid & 7;         // 8 cols (j in A, channels in C)
    const int tr = tid >> 3;        // 16 row-groups of 4

    const float* Qb = g_Q + (size_t)b * N_SPAT * DQK;
    const float* Kb = g_K + (size_t)b * N_SPAT * DQK;
    const float* Vb = g_V + (size_t)b * N_SPAT * DV;

    // ---- load Q tile, transpose, pre-scale by log2(e) ----
    {
        int il = tid >> 1, half = tid & 1;
        float4 q = *(const float4*)(Qb + (size_t)(i0 + il) * DQK + half * 4);
        sQT[(half * 4 + 0) * 64 + il] = q.x * LOG2E_F;
        sQT[(half * 4 + 1) * 64 + il] = q.y * LOG2E_F;
        sQT[(half * 4 + 2) * 64 + il] = q.z * LOG2E_F;
        sQT[(half * 4 + 3) * 64 + il] = q.w * LOG2E_F;
    }

    float m[4], l[4];
    unsigned long long o[4][4];
#pragma unroll
    for (int r = 0; r < 4; ++r) {
        m[r] = -CUDART_INF_F;
        l[r] = 0.f;
#pragma unroll
        for (int c2 = 0; c2 < 4; ++c2) o[r][c2] = 0ull;
    }

    const int NT = N_SPAT / BN;   // 125, exact

    // ---- prologue: stage tile 0 into buffer 0 ----
    {
        float4 kreg = ((const float4*)Kb)[tid];
#pragma unroll
        for (int q = 0; q < 8; ++q)
            cp_async16(&sV[(tid + q * 128) * 4], Vb + (size_t)(tid + q * 128) * 4);
        cp_commit();
        int j = tid >> 1, k0 = (tid & 1) * 4;
        sKT[(k0 + 0) * 64 + j] = kreg.x; sKT[(k0 + 1) * 64 + j] = kreg.y;
        sKT[(k0 + 2) * 64 + j] = kreg.z; sKT[(k0 + 3) * 64 + j] = kreg.w;
        cp_wait0();
        __syncthreads();
    }

    for (int it = 0; it < NT; ++it) {
        const int cur = it & 1;
        const int nxt = cur ^ 1;
        const bool pref = (it + 1 < NT);
        float4 kreg;
        if (pref) {
            int j0n = (it + 1) * BN;
            kreg = ((const float4*)(Kb + (size_t)j0n * DQK))[tid];
            const float* vsrc = Vb + (size_t)j0n * DV;
#pragma unroll
            for (int q = 0; q < 8; ++q)
                cp_async16(&sV[nxt * 4096 + (tid + q * 128) * 4],
                           vsrc + (size_t)(tid + q * 128) * 4);
            cp_commit();
        }

        // ---- phase A: S = Q K^T (4x8 micro-tile, k=8) ----
        float s[4][8];
#pragma unroll
        for (int r = 0; r < 4; ++r)
#pragma unroll
            for (int jj = 0; jj < 8; ++jj) s[r][jj] = 0.f;

#pragma unroll
        for (int k = 0; k < DQK; ++k) {
            float4 q = *(const float4*)&sQT[k * 64 + 4 * tr];
            float4 ka = *(const float4*)&sKT[cur * 512 + k * 64 + 8 * tc];
            float4 kb = *(const float4*)&sKT[cur * 512 + k * 64 + 8 * tc + 4];
            float qv[4] = {q.x, q.y, q.z, q.w};
            float kv[8] = {ka.x, ka.y, ka.z, ka.w, kb.x, kb.y, kb.z, kb.w};
#pragma unroll
            for (int r = 0; r < 4; ++r)
#pragma unroll
                for (int jj = 0; jj < 8; ++jj)
                    s[r][jj] = fmaf(qv[r], kv[jj], s[r][jj]);
        }

        // ---- online softmax (base-2) + publish P via smem ----
#pragma unroll
        for (int r = 0; r < 4; ++r) {
            float mx = s[r][0];
#pragma unroll
            for (int jj = 1; jj < 8; ++jj) mx = fmaxf(mx, s[r][jj]);
            mx = fmaxf(mx, __shfl_xor_sync(0xffffffffu, mx, 1));
            mx = fmaxf(mx, __shfl_xor_sync(0xffffffffu, mx, 2));
            mx = fmaxf(mx, __shfl_xor_sync(0xffffffffu, mx, 4));
            float mnew = fmaxf(m[r], mx);
            float alpha = exp2f(m[r] - mnew);
            m[r] = mnew;
            float rs = 0.f;
#pragma unroll
            for (int jj = 0; jj < 8; ++jj) {
                float p = exp2f(s[r][jj] - mnew);
                s[r][jj] = p;
                rs += p;
            }
            rs += __shfl_xor_sync(0xffffffffu, rs, 1);
            rs += __shfl_xor_sync(0xffffffffu, rs, 2);
            rs += __shfl_xor_sync(0xffffffffu, rs, 4);
            l[r] = l[r] * alpha + rs;
            unsigned long long a2 = dup2(alpha);
#pragma unroll
            for (int c2 = 0; c2 < 4; ++c2) o[r][c2] = mul2(o[r][c2], a2);
            float* pr = &sP[(4 * tr + r) * PSTRIDE + 8 * tc];
            *(float4*)pr       = make_float4(s[r][0], s[r][1], s[r][2], s[r][3]);
            *(float4*)(pr + 4) = make_float4(s[r][4], s[r][5], s[r][6], s[r][7]);
        }
        __syncwarp();   // P producers/consumers are the same warp

        // ---- phase C: O += P @ V (broadcast LDS, FFMA2) ----
#pragma unroll 4
        for (int k0 = 0; k0 < BN; k0 += 4) {
            float p[4][4];
#pragma unroll
            for (int r = 0; r < 4; ++r)
                *(float4*)&p[r][0] = *(const float4*)&sP[(4 * tr + r) * PSTRIDE + k0];
#pragma unroll
            for (int kk = 0; kk < 4; ++kk) {
                const ulonglong2* vp =
                    (const ulonglong2*)&sV[cur * 4096 + (k0 + kk) * 64 + 8 * tc];
                ulonglong2 v01 = vp[0];
                ulonglong2 v23 = vp[1];
#pragma unroll
                for (int r = 0; r < 4; ++r) {
                    unsigned long long pd = dup2(p[r][kk]);
                    fma2(o[r][0], v01.x, pd);
                    fma2(o[r][1], v01.y, pd);
                    fma2(o[r][2], v23.x, pd);
                    fma2(o[r][3], v23.y, pd);
                }
            }
        }

        if (pref) {
            int j = tid >> 1, k0 = (tid & 1) * 4;
            float* kt = &sKT[nxt * 512];
            kt[(k0 + 0) * 64 + j] = kreg.x; kt[(k0 + 1) * 64 + j] = kreg.y;
            kt[(k0 + 2) * 64 + j] = kreg.z; kt[(k0 + 3) * 64 + j] = kreg.w;
        }
        cp_wait0();
        __syncthreads();
    }

    // ---- epilogue: normalize, transpose via smem, coalesced stores ----
    float* sO = sV;   // reuse buffer 0: [c][i_local]
#pragma unroll
    for (int r = 0; r < 4; ++r) {
        float inv = 1.0f / l[r];
        int il = 4 * tr + r;
#pragma unroll
        for (int c2 = 0; c2 < 4; ++c2) {
            int c = 8 * tc + 2 * c2;
            sO[c * 64 + il]       = lo32(o[r][c2]) * inv;
            sO[(c + 1) * 64 + il] = hi32(o[r][c2]) * inv;
        }
    }
    __syncthreads();
    {
        int c = tid >> 1;
        int hh = (tid & 1) * 32;
        float* dst = out + ((size_t)b * DV + c) * N_SPAT + i0 + hh;
        const float* src = &sO[c * 64 + hh];
#pragma unroll
        for (int q = 0; q < 8; ++q)
            ((float4*)dst)[q] = ((const float4*)src)[q];
    }
}

// =====================================================================
extern "C" void kernel_launch(void* const* d_in, const int* in_sizes, int n_in,
                              void* d_out, int out_size)
{
    const float* x  = (const float*)d_in[0];
    const float* wq = (const float*)d_in[1];
    const float* bq = (const float*)d_in[2];
    const float* wk = (const float*)d_in[3];
    const float* bk = (const float*)d_in[4];
    const float* wv = (const float*)d_in[5];
    const float* bv = (const float*)d_in[6];
    float* out = (float*)d_out;

    cudaFuncSetAttribute(attn_kernel,
                         cudaFuncAttributeMaxDynamicSharedMemorySize,
                         SMEM_ATT_BYTES);

    dim3 cgrid(5, 20, 2);                 // ocGroup, z, batch
    conv_qkv_kernel<<<cgrid, CONV_T>>>(x, wq, bq, wk, bk, wv, bv);

    dim3 agrid(N_SPAT / BM, 2);           // 125 x 2 = 250 CTAs
    attn_kernel<<<agrid, ATT_T, SMEM_ATT_BYTES>>>(out);
}

// round 5
// speedup vs baseline: 1.4169x; 1.4169x over previous
#include <cuda_runtime.h>
#include <math_constants.h>

#define N_SPAT 8000
#define CIN 64
#define DQK 8
#define DV 64
#define LOG2E_F 1.4426950408889634f
#define JSPLIT 4

// ---------------- scratch (no allocations allowed) ----------------
__device__ float g_Q[2 * N_SPAT * DQK];             // [b][i][c8]
__device__ float g_K[2 * N_SPAT * DQK];             // [b][j][c8]
__device__ float g_V[2 * N_SPAT * DV];              // [b][j][c64]
__device__ float g_Opart[JSPLIT * 2 * N_SPAT * DV]; // [s][b][i][c]
__device__ float g_m[JSPLIT * 2 * N_SPAT];
__device__ float g_l[JSPLIT * 2 * N_SPAT];

// ---------------- f32x2 helpers (FFMA2 path, sm_10x) ----------------
__device__ __forceinline__ unsigned long long dup2(float x) {
    unsigned long long r;
    asm("mov.b64 %0, {%1, %1};" : "=l"(r) : "r"(__float_as_uint(x)));
    return r;
}
__device__ __forceinline__ unsigned long long pack2(float lo, float hi) {
    unsigned long long r;
    asm("mov.b64 %0, {%1, %2};" : "=l"(r) : "r"(__float_as_uint(lo)), "r"(__float_as_uint(hi)));
    return r;
}
__device__ __forceinline__ void fma2(unsigned long long& d, unsigned long long a, unsigned long long b) {
    asm("fma.rn.f32x2 %0, %1, %2, %0;" : "+l"(d) : "l"(a), "l"(b));
}
__device__ __forceinline__ unsigned long long mul2(unsigned long long a, unsigned long long b) {
    unsigned long long r;
    asm("mul.rn.f32x2 %0, %1, %2;" : "=l"(r) : "l"(a), "l"(b));
    return r;
}
__device__ __forceinline__ float lo32(unsigned long long v) { return __uint_as_float((unsigned)v); }
__device__ __forceinline__ float hi32(unsigned long long v) { return __uint_as_float((unsigned)(v >> 32)); }

// ---------------- cp.async helpers ----------------
__device__ __forceinline__ void cp_async16(void* smem, const void* gmem) {
    unsigned saddr = (unsigned)__cvta_generic_to_shared(smem);
    asm volatile("cp.async.cg.shared.global [%0], [%1], 16;\n" :: "r"(saddr), "l"(gmem));
}
__device__ __forceinline__ void cp_commit() { asm volatile("cp.async.commit_group;\n"); }
__device__ __forceinline__ void cp_wait0() { asm volatile("cp.async.wait_group 0;\n"); }

// =====================================================================
// Conv kernel: fused Q/K/V 3x3x3 SAME conv.
// Grid (5 ocGroups, 40 = z*2+yhalf, 2 b), block 200 (thread per (y,x)
// in a 10-row half-plane). Padded 12x22 slab, ICCHUNK=8 (8 barrier
// phases), f32x2 FMA over oc pairs, vectorized 16B stores.
// =====================================================================
#define CONV_T 200
#define ICCHUNK 8
#define PSY 12
#define PSX 22
#define PS (PSY * PSX)   // 264

__global__ __launch_bounds__(CONV_T) void conv_qkv_kernel(
    const float* __restrict__ x,
    const float* __restrict__ wq, const float* __restrict__ bq,
    const float* __restrict__ wk, const float* __restrict__ bk,
    const float* __restrict__ wv, const float* __restrict__ bv)
{
    __shared__ __align__(16) float slab[ICCHUNK][3][PS];
    __shared__ __align__(16) float wsm[ICCHUNK][27][16];

    const int g = blockIdx.x;
    const int z = blockIdx.y >> 1;
    const int yh = blockIdx.y & 1;
    const int b = blockIdx.z;
    const int tid = threadIdx.x;           // 0..199
    const int yl = tid / 20;               // 0..9
    const int xc = tid % 20;
    const int yg = yh * 10 + yl;
    const int ocbase = g * 16;

    unsigned long long acc[8];
#pragma unroll
    for (int o2 = 0; o2 < 8; ++o2) {
        int oc0 = ocbase + 2 * o2, oc1 = oc0 + 1;
        float b0 = (oc0 < 8) ? bq[oc0] : (oc0 < 16 ? bk[oc0 - 8] : bv[oc0 - 16]);
        float b1 = (oc1 < 8) ? bq[oc1] : (oc1 < 16 ? bk[oc1 - 8] : bv[oc1 - 16]);
        acc[o2] = pack2(b0, b1);
    }

    for (int chunk = 0; chunk < CIN / ICCHUNK; ++chunk) {
        __syncthreads();
        // fill padded input slab (zero borders): rows yh*10-1 .. yh*10+10
        for (int idx = tid; idx < ICCHUNK * 3 * PS; idx += CONV_T) {
            int spl = idx % PS;
            int zz = (idx / PS) % 3;
            int ic = idx / (3 * PS);
            int yy = yh * 10 + spl / PSX - 1;
            int xx = spl % PSX - 1;
            int zg = z + zz - 1;
            float v = 0.f;
            if ((unsigned)zg < 20u && (unsigned)yy < 20u && (unsigned)xx < 20u)
                v = x[(((size_t)b * 64 + chunk * ICCHUNK + ic) * 20 + zg) * 400 + yy * 20 + xx];
            slab[ic][zz][spl] = v;
        }
        // fill weights [ic][tap][ocl]  (oc pairs contiguous for f32x2)
        for (int idx = tid; idx < ICCHUNK * 27 * 16; idx += CONV_T) {
            int ocl = idx & 15;
            int tap = (idx >> 4) % 27;
            int ic = idx / (27 * 16);
            int oc = ocbase + ocl;
            int icg = chunk * ICCHUNK + ic;
            float w;
            if (oc < 8)       w = wq[((size_t)oc * 64 + icg) * 27 + tap];
            else if (oc < 16) w = wk[((size_t)(oc - 8) * 64 + icg) * 27 + tap];
            else              w = wv[((size_t)(oc - 16) * 64 + icg) * 27 + tap];
            wsm[ic][tap][ocl] = w;
        }
        __syncthreads();

#pragma unroll 2
        for (int ic = 0; ic < ICCHUNK; ++ic) {
#pragma unroll
            for (int dz = 0; dz < 3; ++dz) {
                const float* sl = &slab[ic][dz][yl * PSX + xc];
#pragma unroll
                for (int t9 = 0; t9 < 9; ++t9) {
                    const int dy = t9 / 3, dx = t9 % 3;
                    unsigned long long xd = dup2(sl[dy * PSX + dx]);
                    const unsigned long long* wp =
                        (const unsigned long long*)&wsm[ic][dz * 9 + t9][0];
#pragma unroll
                    for (int o2 = 0; o2 < 8; ++o2) fma2(acc[o2], wp[o2], xd);
                }
            }
        }
    }

    // vectorized stores: thread owns 16 consecutive channels for its voxel
    const int i = z * 400 + yg * 20 + xc;
    if (g == 0) {
        float4 a0 = make_float4(lo32(acc[0]), hi32(acc[0]), lo32(acc[1]), hi32(acc[1]));
        float4 a1 = make_float4(lo32(acc[2]), hi32(acc[2]), lo32(acc[3]), hi32(acc[3]));
        float4 a2 = make_float4(lo32(acc[4]), hi32(acc[4]), lo32(acc[5]), hi32(acc[5]));
        float4 a3 = make_float4(lo32(acc[6]), hi32(acc[6]), lo32(acc[7]), hi32(acc[7]));
        float4* qd = (float4*)(g_Q + ((size_t)b * N_SPAT + i) * DQK);
        qd[0] = a0; qd[1] = a1;
        float4* kd = (float4*)(g_K + ((size_t)b * N_SPAT + i) * DQK);
        kd[0] = a2; kd[1] = a3;
    } else {
        float4* vd = (float4*)(g_V + ((size_t)b * N_SPAT + i) * DV + (g - 1) * 16);
#pragma unroll
        for (int q = 0; q < 4; ++q)
            vd[q] = make_float4(lo32(acc[2 * q]), hi32(acc[2 * q]),
                                lo32(acc[2 * q + 1]), hi32(acc[2 * q + 1]));
    }
}

// =====================================================================
// Flash attention kernel (split-KV partials).
// BM=64 rows/CTA, 64 threads (2 warps), 8x8 micro-tile (tr=tid>>3 owns
// rows 8tr..8tr+7, tc=tid&7 owns 8 j-cols / 8 channels).
// grid (125, 2, JSPLIT) = 1000 CTAs -> ~4+ CTAs/SM resident.
// P exchanged by intra-warp shuffle; V tile is 16KB -> 16 cp.async16
// per thread (64 thr x 16 x 16B).
// Writes unnormalized O_part + (m,l) per row; merge_kernel combines.
// =====================================================================
#define BM 64
#define BN 64
#define ATT_T 64

__global__ __launch_bounds__(ATT_T, 4) void attn_kernel()
{
    __shared__ __align__(16) float sQT[DQK][BM];       // Q^T, pre-scaled log2(e)
    __shared__ __align__(16) float sKT[2][DQK][BN];    // K^T per buffer
    __shared__ __align__(16) float sV[2][BN][DV];      // V rows per buffer

    const int b = blockIdx.y;
    const int sp = blockIdx.z;
    const int i0 = blockIdx.x * BM;
    const int tid = threadIdx.x;
    const int tc = tid & 7;
    const int tr = tid >> 3;         // 0..7, rows 8tr..8tr+7
    const int lane = tid & 31;

    const int NTALL = N_SPAT / BN;   // 125
    const int t0 = (sp * NTALL) / JSPLIT;
    const int t1 = ((sp + 1) * NTALL) / JSPLIT;

    const float* Qb = g_Q + (size_t)b * N_SPAT * DQK;
    const float* Kb = g_K + (size_t)b * N_SPAT * DQK;
    const float* Vb = g_V + (size_t)b * N_SPAT * DV;

    // ---- load Q tile (row per thread), transpose, pre-scale ----
    {
        const float4* qp = (const float4*)(Qb + (size_t)(i0 + tid) * DQK);
        float4 q0 = qp[0], q1 = qp[1];
        sQT[0][tid] = q0.x * LOG2E_F; sQT[1][tid] = q0.y * LOG2E_F;
        sQT[2][tid] = q0.z * LOG2E_F; sQT[3][tid] = q0.w * LOG2E_F;
        sQT[4][tid] = q1.x * LOG2E_F; sQT[5][tid] = q1.y * LOG2E_F;
        sQT[6][tid] = q1.z * LOG2E_F; sQT[7][tid] = q1.w * LOG2E_F;
    }

    float m[8], l[8];
    unsigned long long o[8][4];
#pragma unroll
    for (int ii = 0; ii < 8; ++ii) {
        m[ii] = -CUDART_INF_F;
        l[ii] = 0.f;
#pragma unroll
        for (int c2 = 0; c2 < 4; ++c2) o[ii][c2] = 0ull;
    }

    // ---- prologue: stage tile t0 into buffer 0 ----
    {
        const float* ksrc = Kb + (size_t)t0 * BN * DQK;
        float4 k0 = ((const float4*)ksrc)[2 * tid];
        float4 k1 = ((const float4*)ksrc)[2 * tid + 1];
        const float* vsrc = Vb + (size_t)t0 * BN * DV;
#pragma unroll
        for (int q = 0; q < 16; ++q)
            cp_async16(&((float*)sV[0])[(tid + q * 64) * 4], vsrc + (size_t)(tid + q * 64) * 4);
        cp_commit();
        sKT[0][0][tid] = k0.x; sKT[0][1][tid] = k0.y;
        sKT[0][2][tid] = k0.z; sKT[0][3][tid] = k0.w;
        sKT[0][4][tid] = k1.x; sKT[0][5][tid] = k1.y;
        sKT[0][6][tid] = k1.z; sKT[0][7][tid] = k1.w;
        cp_wait0();
        __syncthreads();
    }

    for (int it = t0; it < t1; ++it) {
        const int cur = (it - t0) & 1;
        const int nxt = cur ^ 1;
        const bool pref = (it + 1 < t1);
        float4 k0r, k1r;
        if (pref) {
            const float* ksrc = Kb + (size_t)(it + 1) * BN * DQK;
            k0r = ((const float4*)ksrc)[2 * tid];
            k1r = ((const float4*)ksrc)[2 * tid + 1];
            const float* vsrc = Vb + (size_t)(it + 1) * BN * DV;
#pragma unroll
            for (int q = 0; q < 16; ++q)
                cp_async16(&((float*)sV[nxt])[(tid + q * 64) * 4], vsrc + (size_t)(tid + q * 64) * 4);
            cp_commit();
        }

        // ---- phase A: S = Q K^T (8x8 micro-tile, k=8) ----
        float s[8][8];
#pragma unroll
        for (int ii = 0; ii < 8; ++ii)
#pragma unroll
            for (int jj = 0; jj < 8; ++jj) s[ii][jj] = 0.f;

#pragma unroll
        for (int k = 0; k < DQK; ++k) {
            float4 qa = *(const float4*)&sQT[k][8 * tr];
            float4 qb = *(const float4*)&sQT[k][8 * tr + 4];
            float4 ka = *(const float4*)&sKT[cur][k][8 * tc];
            float4 kb = *(const float4*)&sKT[cur][k][8 * tc + 4];
            float qv[8] = {qa.x, qa.y, qa.z, qa.w, qb.x, qb.y, qb.z, qb.w};
            float kv[8] = {ka.x, ka.y, ka.z, ka.w, kb.x, kb.y, kb.z, kb.w};
#pragma unroll
            for (int ii = 0; ii < 8; ++ii)
#pragma unroll
                for (int jj = 0; jj < 8; ++jj)
                    s[ii][jj] = fmaf(qv[ii], kv[jj], s[ii][jj]);
        }

        // ---- online softmax (base-2 domain) ----
#pragma unroll
        for (int ii = 0; ii < 8; ++ii) {
            float mx = s[ii][0];
#pragma unroll
            for (int jj = 1; jj < 8; ++jj) mx = fmaxf(mx, s[ii][jj]);
            mx = fmaxf(mx, __shfl_xor_sync(0xffffffffu, mx, 1));
            mx = fmaxf(mx, __shfl_xor_sync(0xffffffffu, mx, 2));
            mx = fmaxf(mx, __shfl_xor_sync(0xffffffffu, mx, 4));
            float mnew = fmaxf(m[ii], mx);
            float alpha = exp2f(m[ii] - mnew);
            m[ii] = mnew;
            float rs = 0.f;
#pragma unroll
            for (int jj = 0; jj < 8; ++jj) {
                float p = exp2f(s[ii][jj] - mnew);
                s[ii][jj] = p;          // s now holds P
                rs += p;
            }
            rs += __shfl_xor_sync(0xffffffffu, rs, 1);
            rs += __shfl_xor_sync(0xffffffffu, rs, 2);
            rs += __shfl_xor_sync(0xffffffffu, rs, 4);
            l[ii] = l[ii] * alpha + rs;
            unsigned long long a2 = dup2(alpha);
#pragma unroll
            for (int c2 = 0; c2 < 4; ++c2) o[ii][c2] = mul2(o[ii][c2], a2);
        }

        // ---- phase C: O += P @ V  (P broadcast via shuffle, FFMA2) ----
#pragma unroll
        for (int ko = 0; ko < 8; ++ko) {
#pragma unroll
            for (int jj = 0; jj < 8; ++jj) {
                int k = ko * 8 + jj;
                const ulonglong2* vp = (const ulonglong2*)&sV[cur][k][8 * tc];
                ulonglong2 v01 = vp[0];
                ulonglong2 v23 = vp[1];
                int srcLane = (lane & 24) | ko;
#pragma unroll
                for (int ii = 0; ii < 8; ++ii) {
                    float pv = __shfl_sync(0xffffffffu, s[ii][jj], srcLane);
                    unsigned long long pd = dup2(pv);
                    fma2(o[ii][0], v01.x, pd);
                    fma2(o[ii][1], v01.y, pd);
                    fma2(o[ii][2], v23.x, pd);
                    fma2(o[ii][3], v23.y, pd);
                }
            }
        }

        if (pref) {
            sKT[nxt][0][tid] = k0r.x; sKT[nxt][1][tid] = k0r.y;
            sKT[nxt][2][tid] = k0r.z; sKT[nxt][3][tid] = k0r.w;
            sKT[nxt][4][tid] = k1r.x; sKT[nxt][5][tid] = k1r.y;
            sKT[nxt][6][tid] = k1r.z; sKT[nxt][7][tid] = k1r.w;
        }
        cp_wait0();
        __syncthreads();
    }

    // ---- epilogue: write unnormalized partials + (m,l) ----
    const size_t sb = (size_t)(sp * 2 + b);
#pragma unroll
    for (int ii = 0; ii < 8; ++ii) {
        int i = i0 + 8 * tr + ii;
        float* dst = g_Opart + (sb * N_SPAT + i) * DV + 8 * tc;
        ((float4*)dst)[0] = make_float4(lo32(o[ii][0]), hi32(o[ii][0]),
                                        lo32(o[ii][1]), hi32(o[ii][1]));
        ((float4*)dst)[1] = make_float4(lo32(o[ii][2]), hi32(o[ii][2]),
                                        lo32(o[ii][3]), hi32(o[ii][3]));
        if (tc == 0) {
            g_m[sb * N_SPAT + i] = m[ii];
            g_l[sb * N_SPAT + i] = l[ii];
        }
    }
}

// =====================================================================
// Merge kernel: combine JSPLIT partials (log-sum-exp, base-2 domain),
// transpose via smem, coalesced out[b][c][i] writes.
// Grid (125, 2), 256 threads; block handles 64 rows.
// =====================================================================
__global__ __launch_bounds__(256) void merge_kernel(float* __restrict__ out)
{
    __shared__ float T[DV][65];   // [c][i_local]

    const int b = blockIdx.y;
    const int i0 = blockIdx.x * 64;
    const int tid = threadIdx.x;
    const int il = tid >> 2;          // 0..63
    const int cq = tid & 3;           // channel quad group
    const int i = i0 + il;

    float mm[JSPLIT], coef[JSPLIT];
    float mstar = -CUDART_INF_F;
#pragma unroll
    for (int s = 0; s < JSPLIT; ++s) {
        mm[s] = g_m[((size_t)(s * 2 + b)) * N_SPAT + i];
        mstar = fmaxf(mstar, mm[s]);
    }
    float denom = 0.f;
#pragma unroll
    for (int s = 0; s < JSPLIT; ++s) {
        coef[s] = exp2f(mm[s] - mstar);
        denom += coef[s] * g_l[((size_t)(s * 2 + b)) * N_SPAT + i];
    }
    const float inv = 1.0f / denom;

    float acc[16];
#pragma unroll
    for (int e = 0; e < 16; ++e) acc[e] = 0.f;
#pragma unroll
    for (int s = 0; s < JSPLIT; ++s) {
        const float4* src = (const float4*)(g_Opart +
            (((size_t)(s * 2 + b)) * N_SPAT + i) * DV + cq * 16);
        float c = coef[s];
#pragma unroll
        for (int q = 0; q < 4; ++q) {
            float4 f = src[q];
            acc[4 * q + 0] = fmaf(c, f.x, acc[4 * q + 0]);
            acc[4 * q + 1] = fmaf(c, f.y, acc[4 * q + 1]);
            acc[4 * q + 2] = fmaf(c, f.z, acc[4 * q + 2]);
            acc[4 * q + 3] = fmaf(c, f.w, acc[4 * q + 3]);
        }
    }
#pragma unroll
    for (int e = 0; e < 16; ++e) T[cq * 16 + e][il] = acc[e] * inv;
    __syncthreads();

    {
        const int c = tid >> 2;
        const int ich = (tid & 3) * 16;
        float* dst = out + ((size_t)b * DV + c) * N_SPAT + i0 + ich;
#pragma unroll
        for (int q = 0; q < 4; ++q)
            ((float4*)dst)[q] = make_float4(T[c][ich + 4 * q + 0], T[c][ich + 4 * q + 1],
                                            T[c][ich + 4 * q + 2], T[c][ich + 4 * q + 3]);
    }
}

// =====================================================================
extern "C" void kernel_launch(void* const* d_in, const int* in_sizes, int n_in,
                              void* d_out, int out_size)
{
    const float* x  = (const float*)d_in[0];
    const float* wq = (const float*)d_in[1];
    const float* bq = (const float*)d_in[2];
    const float* wk = (const float*)d_in[3];
    const float* bk = (const float*)d_in[4];
    const float* wv = (const float*)d_in[5];
    const float* bv = (const float*)d_in[6];
    float* out = (float*)d_out;

    dim3 cgrid(5, 40, 2);                 // ocGroup, z*2+yhalf, batch
    conv_qkv_kernel<<<cgrid, CONV_T>>>(x, wq, bq, wk, bk, wv, bv);

    dim3 agrid(N_SPAT / BM, 2, JSPLIT);   // 125 x 2 x 4 = 1000 CTAs
    attn_kernel<<<agrid, ATT_T>>>();

    dim3 mgrid(N_SPAT / 64, 2);
    merge_kernel<<<mgrid, 256>>>(out);
}